// round 1
// baseline (speedup 1.0000x reference)
#include <cuda_runtime.h>
#include <math.h>

#define N_SEQ  4096
#define F_INN  16
#define T_LEN  512
#define HU     64
#define G4     256   // 4*H
#define HID    256
#define NCLASS 10

// ---------------- scratch (no allocation allowed) ----------------
__device__ float g_X[N_SEQ * T_LEN];                  // (N, T) first hidden channel of layer-1
__device__ float g_adj[(size_t)N_SEQ * N_SEQ];        // unnormalized adjacency (corr + I)
__device__ float g_mu[N_SEQ];
__device__ float g_sd[N_SEQ];
__device__ float g_d[N_SEQ];                          // D^-1/2 diag
__device__ float g_Z[N_SEQ * HID];
__device__ float g_Y1[N_SEQ * HID];
__device__ float g_Y2[N_SEQ * HID];

__device__ __forceinline__ float sigf(float x) { return 1.0f / (1.0f + expf(-x)); }

// ============================================================================
// Fused 2-layer LSTM. Each block owns 16 sequences for all 512 timesteps.
// Weights in SMEM, gate-interleaved [(k)][(u*4+gate)] so one float4 read gives
// the 4 gate weights for hidden unit u at reduction index k.
// Thread mapping: tid = u*8 + sg ; u in [0,64), sg in [0,8).
// Thread handles sequences s0=sg, s1=sg+8 at hidden unit u; c-state in regs.
// ============================================================================
#define SPB 16                  // sequences per block
#define LSTM_THREADS 512

// smem float offsets
#define OFF_WIH0 0              // 16*256
#define OFF_WHH0 4096           // 64*256
#define OFF_WIH1 20480          // 64*256
#define OFF_WHH1 36864          // 64*256
#define OFF_B0   53248          // 256
#define OFF_B1   53504          // 256
#define OFF_H0   53760          // 16*65
#define OFF_H1   54800          // 16*65
#define OFF_SX   55840          // 16*17
#define LSTM_SMEM_FLOATS 56112
#define LSTM_SMEM_BYTES (LSTM_SMEM_FLOATS * 4)

#define GATE8(w, ha, hb)                                               \
    Aa.x += (ha) * (w).x; Aa.y += (ha) * (w).y;                        \
    Aa.z += (ha) * (w).z; Aa.w += (ha) * (w).w;                        \
    Ab.x += (hb) * (w).x; Ab.y += (hb) * (w).y;                        \
    Ab.z += (hb) * (w).z; Ab.w += (hb) * (w).w;

__global__ void __launch_bounds__(LSTM_THREADS, 1)
lstm_kernel(const float* __restrict__ feat,
            const float* __restrict__ wih0, const float* __restrict__ whh0,
            const float* __restrict__ bih0, const float* __restrict__ bhh0,
            const float* __restrict__ wih1, const float* __restrict__ whh1,
            const float* __restrict__ bih1, const float* __restrict__ bhh1,
            float* __restrict__ Xout)
{
    extern __shared__ float sm[];
    float* sWih0 = sm + OFF_WIH0;
    float* sWhh0 = sm + OFF_WHH0;
    float* sWih1 = sm + OFF_WIH1;
    float* sWhh1 = sm + OFF_WHH1;
    float* sb0   = sm + OFF_B0;
    float* sb1   = sm + OFF_B1;
    float* sh0   = sm + OFF_H0;
    float* sh1   = sm + OFF_H1;
    float* sx    = sm + OFF_SX;

    const int tid = threadIdx.x;
    const int nbase = blockIdx.x * SPB;

    // ---- stage weights (transposed + gate-interleaved) ----
    for (int idx = tid; idx < HU * G4; idx += LSTM_THREADS) {
        int k = idx >> 8, r = idx & 255, u = r >> 2, g = r & 3;
        int j = g * HU + u;
        sWhh0[idx] = whh0[j * HU + k];
        sWih1[idx] = wih1[j * HU + k];
        sWhh1[idx] = whh1[j * HU + k];
    }
    for (int idx = tid; idx < F_INN * G4; idx += LSTM_THREADS) {
        int f = idx >> 8, r = idx & 255, u = r >> 2, g = r & 3;
        int j = g * HU + u;
        sWih0[idx] = wih0[j * F_INN + f];
    }
    if (tid < G4) {
        int u = tid >> 2, g = tid & 3, j = g * HU + u;
        sb0[tid] = bih0[j] + bhh0[j];
        sb1[tid] = bih1[j] + bhh1[j];
    }
    for (int idx = tid; idx < SPB * 65; idx += LSTM_THREADS) { sh0[idx] = 0.f; sh1[idx] = 0.f; }
    if (tid < SPB * F_INN) {
        int s = tid >> 4, f = tid & 15;
        sx[s * 17 + f] = feat[(size_t)(nbase + s) * (F_INN * T_LEN) + f * T_LEN + 0];
    }
    __syncthreads();

    const int u  = tid >> 3;
    const int sg = tid & 7;
    const int s0 = sg, s1 = sg + 8;

    const float4* W0i4 = (const float4*)sWih0;
    const float4* W0h4 = (const float4*)sWhh0;
    const float4* W1i4 = (const float4*)sWih1;
    const float4* W1h4 = (const float4*)sWhh1;
    const float4 b0v = ((const float4*)sb0)[u];
    const float4 b1v = ((const float4*)sb1)[u];

    float c0a = 0.f, c0b = 0.f, c1a = 0.f, c1b = 0.f;

    for (int t = 0; t < T_LEN; ++t) {
        // -------- layer 0 gates --------
        float4 Aa = b0v, Ab = b0v;
        #pragma unroll
        for (int f = 0; f < F_INN; ++f) {
            float4 w = W0i4[(f << 6) + u];
            float xa = sx[s0 * 17 + f], xb = sx[s1 * 17 + f];
            GATE8(w, xa, xb);
        }
        #pragma unroll 16
        for (int k = 0; k < HU; ++k) {
            float4 w = W0h4[(k << 6) + u];
            float ha = sh0[s0 * 65 + k], hb = sh0[s1 * 65 + k];
            GATE8(w, ha, hb);
        }
        c0a = sigf(Aa.y) * c0a + sigf(Aa.x) * tanhf(Aa.z);
        float h0a = sigf(Aa.w) * tanhf(c0a);
        c0b = sigf(Ab.y) * c0b + sigf(Ab.x) * tanhf(Ab.z);
        float h0b = sigf(Ab.w) * tanhf(c0b);
        __syncthreads();
        sh0[s0 * 65 + u] = h0a;
        sh0[s1 * 65 + u] = h0b;
        __syncthreads();

        // -------- layer 1 gates --------
        Aa = b1v; Ab = b1v;
        #pragma unroll 16
        for (int k = 0; k < HU; ++k) {
            float4 w = W1i4[(k << 6) + u];
            float ha = sh0[s0 * 65 + k], hb = sh0[s1 * 65 + k];
            GATE8(w, ha, hb);
        }
        #pragma unroll 16
        for (int k = 0; k < HU; ++k) {
            float4 w = W1h4[(k << 6) + u];
            float ha = sh1[s0 * 65 + k], hb = sh1[s1 * 65 + k];
            GATE8(w, ha, hb);
        }
        c1a = sigf(Aa.y) * c1a + sigf(Aa.x) * tanhf(Aa.z);
        float h1a = sigf(Aa.w) * tanhf(c1a);
        c1b = sigf(Ab.y) * c1b + sigf(Ab.x) * tanhf(Ab.z);
        float h1b = sigf(Ab.w) * tanhf(c1b);
        __syncthreads();
        sh1[s0 * 65 + u] = h1a;
        sh1[s1 * 65 + u] = h1b;
        if (u == 0) {
            Xout[(size_t)(nbase + s0) * T_LEN + t] = h1a;
            Xout[(size_t)(nbase + s1) * T_LEN + t] = h1b;
        }
        if (tid < SPB * F_INN && t + 1 < T_LEN) {
            int s = tid >> 4, f = tid & 15;
            sx[s * 17 + f] = feat[(size_t)(nbase + s) * (F_INN * T_LEN) + f * T_LEN + (t + 1)];
        }
        __syncthreads();
    }
}

// ============================================================================
// Row stats: mu, std per row of X (N, T)
// ============================================================================
__global__ void rowstats_kernel(const float* __restrict__ X,
                                float* __restrict__ mu, float* __restrict__ sd)
{
    __shared__ float s1[4], s2[4];
    int n = blockIdx.x;
    float a = 0.f, b = 0.f;
    for (int i = threadIdx.x; i < T_LEN; i += 128) {
        float v = X[(size_t)n * T_LEN + i];
        a += v; b += v * v;
    }
    #pragma unroll
    for (int o = 16; o; o >>= 1) {
        a += __shfl_xor_sync(0xffffffffu, a, o);
        b += __shfl_xor_sync(0xffffffffu, b, o);
    }
    int w = threadIdx.x >> 5;
    if ((threadIdx.x & 31) == 0) { s1[w] = a; s2[w] = b; }
    __syncthreads();
    if (threadIdx.x == 0) {
        a = s1[0] + s1[1] + s1[2] + s1[3];
        b = s2[0] + s2[1] + s2[2] + s2[3];
        float m = a * (1.0f / T_LEN);
        float var = b * (1.0f / T_LEN) - m * m;
        if (var < 0.f) var = 0.f;
        mu[n] = m;
        sd[n] = sqrtf(var);
    }
}

// ============================================================================
// Generic register-tiled fp32 GEMM. C = A(MxK) @ B(KxN)  (TB=1: B = Bphys^T,
// Bphys is NxK row-major). Epilogues:
//   EPI 0: adjacency from Gram matrix (needs mu, sd)
//   EPI 1: scale rows by dd[row]
//   EPI 2: relu(dd[row]*v + bias[col])
// ============================================================================
template<int BM, int BN, int BK, int TM, int TN, int TB, int EPI>
__global__ void gemm_kernel(const float* __restrict__ A, const float* __restrict__ B,
                            float* __restrict__ C, int M, int N, int K,
                            const float* __restrict__ dd, const float* __restrict__ bias,
                            const float* __restrict__ mu, const float* __restrict__ sd)
{
    constexpr int TX = BN / TN;
    constexpr int TY = BM / TM;
    constexpr int THREADS = TX * TY;
    __shared__ float As[BK][BM + 4];
    __shared__ float Bs[BK][BN + 4];

    const int t  = threadIdx.x;
    const int bm = blockIdx.y * BM;
    const int bn = blockIdx.x * BN;
    const int tx = t % TX;
    const int ty = t / TX;

    float acc[TM][TN];
    #pragma unroll
    for (int i = 0; i < TM; ++i)
        #pragma unroll
        for (int j = 0; j < TN; ++j) acc[i][j] = 0.f;

    for (int k0 = 0; k0 < K; k0 += BK) {
        // load A tile (BM x BK), transposed into As[k][m]
        constexpr int A4 = BM * BK / 4;
        #pragma unroll
        for (int i = t; i < A4; i += THREADS) {
            int row = i / (BK / 4), kc = (i % (BK / 4)) * 4;
            float4 v = *(const float4*)&A[(size_t)(bm + row) * K + k0 + kc];
            As[kc + 0][row] = v.x; As[kc + 1][row] = v.y;
            As[kc + 2][row] = v.z; As[kc + 3][row] = v.w;
        }
        if (TB == 0) {
            constexpr int B4 = BK * BN / 4;
            #pragma unroll
            for (int i = t; i < B4; i += THREADS) {
                int row = i / (BN / 4), nc = (i % (BN / 4)) * 4;
                float4 v = *(const float4*)&B[(size_t)(k0 + row) * N + bn + nc];
                Bs[row][nc + 0] = v.x; Bs[row][nc + 1] = v.y;
                Bs[row][nc + 2] = v.z; Bs[row][nc + 3] = v.w;
            }
        } else {
            constexpr int B4 = BN * BK / 4;
            #pragma unroll
            for (int i = t; i < B4; i += THREADS) {
                int col = i / (BK / 4), kc = (i % (BK / 4)) * 4;
                float4 v = *(const float4*)&B[(size_t)(bn + col) * K + k0 + kc];
                Bs[kc + 0][col] = v.x; Bs[kc + 1][col] = v.y;
                Bs[kc + 2][col] = v.z; Bs[kc + 3][col] = v.w;
            }
        }
        __syncthreads();
        #pragma unroll
        for (int k = 0; k < BK; ++k) {
            float ra[TM], rb[TN];
            #pragma unroll
            for (int i = 0; i < TM; ++i) ra[i] = As[k][ty * TM + i];
            #pragma unroll
            for (int j = 0; j < TN; ++j) rb[j] = Bs[k][tx * TN + j];
            #pragma unroll
            for (int i = 0; i < TM; ++i)
                #pragma unroll
                for (int j = 0; j < TN; ++j) acc[i][j] += ra[i] * rb[j];
        }
        __syncthreads();
    }

    #pragma unroll
    for (int i = 0; i < TM; ++i) {
        int row = bm + ty * TM + i;
        #pragma unroll
        for (int j = 0; j < TN; ++j) {
            int col = bn + tx * TN + j;
            float v = acc[i][j];
            if (EPI == 0) {
                float cov = v * (1.0f / T_LEN) - mu[row] * mu[col];
                float den = sd[row] * sd[col];
                v = (den == 0.0f) ? 0.0f : cov / den;
                if (row == col) v += 1.0f;
            } else if (EPI == 1) {
                v *= dd[row];
            } else if (EPI == 2) {
                v = dd[row] * v + bias[col];
                v = fmaxf(v, 0.0f);
            }
            C[(size_t)row * N + col] = v;
        }
    }
}

// ============================================================================
// Row-sum of adjacency -> d = rs>0 ? rs^-1/2 : 0
// ============================================================================
__global__ void rowsumd_kernel(const float* __restrict__ adj, float* __restrict__ d)
{
    __shared__ float sr[8];
    int n = blockIdx.x;
    float a = 0.f;
    for (int j = threadIdx.x; j < N_SEQ; j += 256) a += adj[(size_t)n * N_SEQ + j];
    #pragma unroll
    for (int o = 16; o; o >>= 1) a += __shfl_xor_sync(0xffffffffu, a, o);
    int w = threadIdx.x >> 5;
    if ((threadIdx.x & 31) == 0) sr[w] = a;
    __syncthreads();
    if (threadIdx.x == 0) {
        a = 0.f;
        #pragma unroll
        for (int i = 0; i < 8; ++i) a += sr[i];
        d[n] = (a > 0.0f) ? (1.0f / sqrtf(a)) : 0.0f;
    }
}

// ============================================================================
// Classifier: out = Y2 @ clf_w + clf_b ; one warp per row
// ============================================================================
__global__ void clf_kernel(const float* __restrict__ Y, const float* __restrict__ W,
                           const float* __restrict__ b, float* __restrict__ out)
{
    int warp = threadIdx.x >> 5, lane = threadIdx.x & 31;
    int n = blockIdx.x * 8 + warp;
    float p[NCLASS];
    #pragma unroll
    for (int c = 0; c < NCLASS; ++c) p[c] = 0.f;
    for (int k = lane; k < HID; k += 32) {
        float x = Y[(size_t)n * HID + k];
        #pragma unroll
        for (int c = 0; c < NCLASS; ++c) p[c] += x * W[k * NCLASS + c];
    }
    #pragma unroll
    for (int c = 0; c < NCLASS; ++c)
        #pragma unroll
        for (int o = 16; o; o >>= 1) p[c] += __shfl_xor_sync(0xffffffffu, p[c], o);
    if (lane < NCLASS) out[(size_t)n * NCLASS + lane] = p[lane] + b[lane];
}

// ============================================================================
extern "C" void kernel_launch(void* const* d_in, const int* in_sizes, int n_in,
                              void* d_out, int out_size)
{
    const float* feat  = (const float*)d_in[0];
    const float* wih0  = (const float*)d_in[1];
    const float* whh0  = (const float*)d_in[2];
    const float* bih0  = (const float*)d_in[3];
    const float* bhh0  = (const float*)d_in[4];
    const float* wih1  = (const float*)d_in[5];
    const float* whh1  = (const float*)d_in[6];
    const float* bih1  = (const float*)d_in[7];
    const float* bhh1  = (const float*)d_in[8];
    const float* gc1w  = (const float*)d_in[9];
    const float* gc1b  = (const float*)d_in[10];
    const float* gc2w  = (const float*)d_in[11];
    const float* gc2b  = (const float*)d_in[12];
    const float* clfw  = (const float*)d_in[13];
    const float* clfb  = (const float*)d_in[14];
    float* out = (float*)d_out;

    float *pX, *pAdj, *pMu, *pSd, *pD, *pZ, *pY1, *pY2;
    cudaGetSymbolAddress((void**)&pX,  g_X);
    cudaGetSymbolAddress((void**)&pAdj, g_adj);
    cudaGetSymbolAddress((void**)&pMu, g_mu);
    cudaGetSymbolAddress((void**)&pSd, g_sd);
    cudaGetSymbolAddress((void**)&pD,  g_d);
    cudaGetSymbolAddress((void**)&pZ,  g_Z);
    cudaGetSymbolAddress((void**)&pY1, g_Y1);
    cudaGetSymbolAddress((void**)&pY2, g_Y2);

    cudaFuncSetAttribute(lstm_kernel, cudaFuncAttributeMaxDynamicSharedMemorySize,
                         LSTM_SMEM_BYTES);

    // 1) fused 2-layer LSTM -> X (N, T)
    lstm_kernel<<<N_SEQ / SPB, LSTM_THREADS, LSTM_SMEM_BYTES>>>(
        feat, wih0, whh0, bih0, bhh0, wih1, whh1, bih1, bhh1, pX);

    // 2) per-row mean/std
    rowstats_kernel<<<N_SEQ, 128>>>(pX, pMu, pSd);

    // 3) adjacency = corr(X) + I  (Gram matrix with fused epilogue)
    gemm_kernel<128, 128, 8, 8, 8, 1, 0><<<dim3(N_SEQ / 128, N_SEQ / 128), 256>>>(
        pX, pX, pAdj, N_SEQ, N_SEQ, T_LEN, nullptr, nullptr, pMu, pSd);

    // 4) d = rowsum(adj)^-1/2 (0 if rowsum <= 0)
    rowsumd_kernel<<<N_SEQ, 256>>>(pAdj, pD);

    // 5) Z = d ⊙ (X @ gc1_w)
    gemm_kernel<128, 64, 8, 8, 4, 0, 1><<<dim3(HID / 64, N_SEQ / 128), 256>>>(
        pX, gc1w, pZ, N_SEQ, HID, T_LEN, pD, nullptr, nullptr, nullptr);

    // 6) Y1 = relu(d ⊙ (adj @ Z) + gc1_b)
    gemm_kernel<128, 64, 8, 8, 4, 0, 2><<<dim3(HID / 64, N_SEQ / 128), 256>>>(
        pAdj, pZ, pY1, N_SEQ, HID, N_SEQ, pD, gc1b, nullptr, nullptr);

    // 7) Z = d ⊙ (Y1 @ gc2_w)
    gemm_kernel<128, 64, 8, 8, 4, 0, 1><<<dim3(HID / 64, N_SEQ / 128), 256>>>(
        pY1, gc2w, pZ, N_SEQ, HID, HID, pD, nullptr, nullptr, nullptr);

    // 8) Y2 = relu(d ⊙ (adj @ Z) + gc2_b)
    gemm_kernel<128, 64, 8, 8, 4, 0, 2><<<dim3(HID / 64, N_SEQ / 128), 256>>>(
        pAdj, pZ, pY2, N_SEQ, HID, N_SEQ, pD, gc2b, nullptr, nullptr);

    // 9) out = Y2 @ clf_w + clf_b
    clf_kernel<<<N_SEQ / 8, 256>>>(pY2, clfw, clfb, out);
}

// round 3
// speedup vs baseline: 1.0014x; 1.0014x over previous
#include <cuda_runtime.h>
#include <math.h>

#define N_SEQ  4096
#define F_INN  16
#define T_LEN  512
#define HU     64
#define G4     256   // 4*H
#define HID    256
#define NCLASS 10

// ---------------- scratch (no allocation allowed) ----------------
__device__ float g_X[N_SEQ * T_LEN];                  // (N, T) first hidden channel of layer-1
__device__ float g_adj[(size_t)N_SEQ * N_SEQ];        // unnormalized adjacency (corr + I)
__device__ float g_mu[N_SEQ];
__device__ float g_sd[N_SEQ];
__device__ float g_d[N_SEQ];                          // D^-1/2 diag
__device__ float g_Z[N_SEQ * HID];
__device__ float g_Y1[N_SEQ * HID];
__device__ float g_Y2[N_SEQ * HID];

__device__ __forceinline__ float sigf(float x) { return 1.0f / (1.0f + expf(-x)); }

// ============================================================================
// Fused 2-layer LSTM. Each block owns 16 sequences for all 512 timesteps.
// Weights in SMEM, gate-interleaved [(k)][(u*4+gate)] so one float4 read gives
// the 4 gate weights for hidden unit u at reduction index k.
// Thread mapping: tid = u*8 + sg ; u in [0,64), sg in [0,8).
// Thread handles sequences s0=sg, s1=sg+8 at hidden unit u; c-state in regs.
// ============================================================================
#define SPB 16                  // sequences per block
#define LSTM_THREADS 512

// smem float offsets
#define OFF_WIH0 0              // 16*256
#define OFF_WHH0 4096           // 64*256
#define OFF_WIH1 20480          // 64*256
#define OFF_WHH1 36864          // 64*256
#define OFF_B0   53248          // 256
#define OFF_B1   53504          // 256
#define OFF_H0   53760          // 16*65
#define OFF_H1   54800          // 16*65
#define OFF_SX   55840          // 16*17
#define LSTM_SMEM_FLOATS 56112
#define LSTM_SMEM_BYTES (LSTM_SMEM_FLOATS * 4)

#define GATE8(w, ha, hb)                                               \
    Aa.x += (ha) * (w).x; Aa.y += (ha) * (w).y;                        \
    Aa.z += (ha) * (w).z; Aa.w += (ha) * (w).w;                        \
    Ab.x += (hb) * (w).x; Ab.y += (hb) * (w).y;                        \
    Ab.z += (hb) * (w).z; Ab.w += (hb) * (w).w;

__global__ void __launch_bounds__(LSTM_THREADS, 1)
lstm_kernel(const float* __restrict__ feat,
            const float* __restrict__ wih0, const float* __restrict__ whh0,
            const float* __restrict__ bih0, const float* __restrict__ bhh0,
            const float* __restrict__ wih1, const float* __restrict__ whh1,
            const float* __restrict__ bih1, const float* __restrict__ bhh1,
            float* __restrict__ Xout)
{
    extern __shared__ float sm[];
    float* sWih0 = sm + OFF_WIH0;
    float* sWhh0 = sm + OFF_WHH0;
    float* sWih1 = sm + OFF_WIH1;
    float* sWhh1 = sm + OFF_WHH1;
    float* sb0   = sm + OFF_B0;
    float* sb1   = sm + OFF_B1;
    float* sh0   = sm + OFF_H0;
    float* sh1   = sm + OFF_H1;
    float* sx    = sm + OFF_SX;

    const int tid = threadIdx.x;
    const int nbase = blockIdx.x * SPB;

    // ---- stage weights (transposed + gate-interleaved) ----
    for (int idx = tid; idx < HU * G4; idx += LSTM_THREADS) {
        int k = idx >> 8, r = idx & 255, u = r >> 2, g = r & 3;
        int j = g * HU + u;
        sWhh0[idx] = whh0[j * HU + k];
        sWih1[idx] = wih1[j * HU + k];
        sWhh1[idx] = whh1[j * HU + k];
    }
    for (int idx = tid; idx < F_INN * G4; idx += LSTM_THREADS) {
        int f = idx >> 8, r = idx & 255, u = r >> 2, g = r & 3;
        int j = g * HU + u;
        sWih0[idx] = wih0[j * F_INN + f];
    }
    if (tid < G4) {
        int u = tid >> 2, g = tid & 3, j = g * HU + u;
        sb0[tid] = bih0[j] + bhh0[j];
        sb1[tid] = bih1[j] + bhh1[j];
    }
    for (int idx = tid; idx < SPB * 65; idx += LSTM_THREADS) { sh0[idx] = 0.f; sh1[idx] = 0.f; }
    if (tid < SPB * F_INN) {
        int s = tid >> 4, f = tid & 15;
        sx[s * 17 + f] = feat[(size_t)(nbase + s) * (F_INN * T_LEN) + f * T_LEN + 0];
    }
    __syncthreads();

    const int u  = tid >> 3;
    const int sg = tid & 7;
    const int s0 = sg, s1 = sg + 8;

    const float4* W0i4 = (const float4*)sWih0;
    const float4* W0h4 = (const float4*)sWhh0;
    const float4* W1i4 = (const float4*)sWih1;
    const float4* W1h4 = (const float4*)sWhh1;
    const float4 b0v = ((const float4*)sb0)[u];
    const float4 b1v = ((const float4*)sb1)[u];

    float c0a = 0.f, c0b = 0.f, c1a = 0.f, c1b = 0.f;

    for (int t = 0; t < T_LEN; ++t) {
        // -------- layer 0 gates --------
        float4 Aa = b0v, Ab = b0v;
        #pragma unroll
        for (int f = 0; f < F_INN; ++f) {
            float4 w = W0i4[(f << 6) + u];
            float xa = sx[s0 * 17 + f], xb = sx[s1 * 17 + f];
            GATE8(w, xa, xb);
        }
        #pragma unroll 16
        for (int k = 0; k < HU; ++k) {
            float4 w = W0h4[(k << 6) + u];
            float ha = sh0[s0 * 65 + k], hb = sh0[s1 * 65 + k];
            GATE8(w, ha, hb);
        }
        c0a = sigf(Aa.y) * c0a + sigf(Aa.x) * tanhf(Aa.z);
        float h0a = sigf(Aa.w) * tanhf(c0a);
        c0b = sigf(Ab.y) * c0b + sigf(Ab.x) * tanhf(Ab.z);
        float h0b = sigf(Ab.w) * tanhf(c0b);
        __syncthreads();
        sh0[s0 * 65 + u] = h0a;
        sh0[s1 * 65 + u] = h0b;
        __syncthreads();

        // -------- layer 1 gates --------
        Aa = b1v; Ab = b1v;
        #pragma unroll 16
        for (int k = 0; k < HU; ++k) {
            float4 w = W1i4[(k << 6) + u];
            float ha = sh0[s0 * 65 + k], hb = sh0[s1 * 65 + k];
            GATE8(w, ha, hb);
        }
        #pragma unroll 16
        for (int k = 0; k < HU; ++k) {
            float4 w = W1h4[(k << 6) + u];
            float ha = sh1[s0 * 65 + k], hb = sh1[s1 * 65 + k];
            GATE8(w, ha, hb);
        }
        c1a = sigf(Aa.y) * c1a + sigf(Aa.x) * tanhf(Aa.z);
        float h1a = sigf(Aa.w) * tanhf(c1a);
        c1b = sigf(Ab.y) * c1b + sigf(Ab.x) * tanhf(Ab.z);
        float h1b = sigf(Ab.w) * tanhf(c1b);
        __syncthreads();
        sh1[s0 * 65 + u] = h1a;
        sh1[s1 * 65 + u] = h1b;
        if (u == 0) {
            Xout[(size_t)(nbase + s0) * T_LEN + t] = h1a;
            Xout[(size_t)(nbase + s1) * T_LEN + t] = h1b;
        }
        if (tid < SPB * F_INN && t + 1 < T_LEN) {
            int s = tid >> 4, f = tid & 15;
            sx[s * 17 + f] = feat[(size_t)(nbase + s) * (F_INN * T_LEN) + f * T_LEN + (t + 1)];
        }
        __syncthreads();
    }
}

// ============================================================================
// Row stats: mu, std per row of X (N, T)
// ============================================================================
__global__ void rowstats_kernel(const float* __restrict__ X,
                                float* __restrict__ mu, float* __restrict__ sd)
{
    __shared__ float s1[4], s2[4];
    int n = blockIdx.x;
    float a = 0.f, b = 0.f;
    for (int i = threadIdx.x; i < T_LEN; i += 128) {
        float v = X[(size_t)n * T_LEN + i];
        a += v; b += v * v;
    }
    #pragma unroll
    for (int o = 16; o; o >>= 1) {
        a += __shfl_xor_sync(0xffffffffu, a, o);
        b += __shfl_xor_sync(0xffffffffu, b, o);
    }
    int w = threadIdx.x >> 5;
    if ((threadIdx.x & 31) == 0) { s1[w] = a; s2[w] = b; }
    __syncthreads();
    if (threadIdx.x == 0) {
        a = s1[0] + s1[1] + s1[2] + s1[3];
        b = s2[0] + s2[1] + s2[2] + s2[3];
        float m = a * (1.0f / T_LEN);
        float var = b * (1.0f / T_LEN) - m * m;
        if (var < 0.f) var = 0.f;
        mu[n] = m;
        sd[n] = sqrtf(var);
    }
}

// ============================================================================
// Generic register-tiled fp32 GEMM. C = A(MxK) @ B(KxN)  (TB=1: B = Bphys^T,
// Bphys is NxK row-major). Epilogues:
//   EPI 0: adjacency from Gram matrix (needs mu, sd)
//   EPI 1: scale rows by dd[row]
//   EPI 2: relu(dd[row]*v + bias[col])
// ============================================================================
template<int BM, int BN, int BK, int TM, int TN, int TB, int EPI>
__global__ void gemm_kernel(const float* __restrict__ A, const float* __restrict__ B,
                            float* __restrict__ C, int M, int N, int K,
                            const float* __restrict__ dd, const float* __restrict__ bias,
                            const float* __restrict__ mu, const float* __restrict__ sd)
{
    constexpr int TX = BN / TN;
    constexpr int TY = BM / TM;
    constexpr int THREADS = TX * TY;
    __shared__ float As[BK][BM + 4];
    __shared__ float Bs[BK][BN + 4];

    const int t  = threadIdx.x;
    const int bm = blockIdx.y * BM;
    const int bn = blockIdx.x * BN;
    const int tx = t % TX;
    const int ty = t / TX;

    float acc[TM][TN];
    #pragma unroll
    for (int i = 0; i < TM; ++i)
        #pragma unroll
        for (int j = 0; j < TN; ++j) acc[i][j] = 0.f;

    for (int k0 = 0; k0 < K; k0 += BK) {
        // load A tile (BM x BK), transposed into As[k][m]
        constexpr int A4 = BM * BK / 4;
        #pragma unroll
        for (int i = t; i < A4; i += THREADS) {
            int row = i / (BK / 4), kc = (i % (BK / 4)) * 4;
            float4 v = *(const float4*)&A[(size_t)(bm + row) * K + k0 + kc];
            As[kc + 0][row] = v.x; As[kc + 1][row] = v.y;
            As[kc + 2][row] = v.z; As[kc + 3][row] = v.w;
        }
        if (TB == 0) {
            constexpr int B4 = BK * BN / 4;
            #pragma unroll
            for (int i = t; i < B4; i += THREADS) {
                int row = i / (BN / 4), nc = (i % (BN / 4)) * 4;
                float4 v = *(const float4*)&B[(size_t)(k0 + row) * N + bn + nc];
                Bs[row][nc + 0] = v.x; Bs[row][nc + 1] = v.y;
                Bs[row][nc + 2] = v.z; Bs[row][nc + 3] = v.w;
            }
        } else {
            constexpr int B4 = BN * BK / 4;
            #pragma unroll
            for (int i = t; i < B4; i += THREADS) {
                int col = i / (BK / 4), kc = (i % (BK / 4)) * 4;
                float4 v = *(const float4*)&B[(size_t)(bn + col) * K + k0 + kc];
                Bs[kc + 0][col] = v.x; Bs[kc + 1][col] = v.y;
                Bs[kc + 2][col] = v.z; Bs[kc + 3][col] = v.w;
            }
        }
        __syncthreads();
        #pragma unroll
        for (int k = 0; k < BK; ++k) {
            float ra[TM], rb[TN];
            #pragma unroll
            for (int i = 0; i < TM; ++i) ra[i] = As[k][ty * TM + i];
            #pragma unroll
            for (int j = 0; j < TN; ++j) rb[j] = Bs[k][tx * TN + j];
            #pragma unroll
            for (int i = 0; i < TM; ++i)
                #pragma unroll
                for (int j = 0; j < TN; ++j) acc[i][j] += ra[i] * rb[j];
        }
        __syncthreads();
    }

    #pragma unroll
    for (int i = 0; i < TM; ++i) {
        int row = bm + ty * TM + i;
        #pragma unroll
        for (int j = 0; j < TN; ++j) {
            int col = bn + tx * TN + j;
            float v = acc[i][j];
            if (EPI == 0) {
                float cov = v * (1.0f / T_LEN) - mu[row] * mu[col];
                float den = sd[row] * sd[col];
                v = (den == 0.0f) ? 0.0f : cov / den;
                if (row == col) v += 1.0f;
            } else if (EPI == 1) {
                v *= dd[row];
            } else if (EPI == 2) {
                v = dd[row] * v + bias[col];
                v = fmaxf(v, 0.0f);
            }
            C[(size_t)row * N + col] = v;
        }
    }
}

// ============================================================================
// Row-sum of adjacency -> d = rs>0 ? rs^-1/2 : 0
// ============================================================================
__global__ void rowsumd_kernel(const float* __restrict__ adj, float* __restrict__ d)
{
    __shared__ float sr[8];
    int n = blockIdx.x;
    float a = 0.f;
    for (int j = threadIdx.x; j < N_SEQ; j += 256) a += adj[(size_t)n * N_SEQ + j];
    #pragma unroll
    for (int o = 16; o; o >>= 1) a += __shfl_xor_sync(0xffffffffu, a, o);
    int w = threadIdx.x >> 5;
    if ((threadIdx.x & 31) == 0) sr[w] = a;
    __syncthreads();
    if (threadIdx.x == 0) {
        a = 0.f;
        #pragma unroll
        for (int i = 0; i < 8; ++i) a += sr[i];
        d[n] = (a > 0.0f) ? (1.0f / sqrtf(a)) : 0.0f;
    }
}

// ============================================================================
// Classifier: out = Y2 @ clf_w + clf_b ; one warp per row
// ============================================================================
__global__ void clf_kernel(const float* __restrict__ Y, const float* __restrict__ W,
                           const float* __restrict__ b, float* __restrict__ out)
{
    int warp = threadIdx.x >> 5, lane = threadIdx.x & 31;
    int n = blockIdx.x * 8 + warp;
    float p[NCLASS];
    #pragma unroll
    for (int c = 0; c < NCLASS; ++c) p[c] = 0.f;
    for (int k = lane; k < HID; k += 32) {
        float x = Y[(size_t)n * HID + k];
        #pragma unroll
        for (int c = 0; c < NCLASS; ++c) p[c] += x * W[k * NCLASS + c];
    }
    #pragma unroll
    for (int c = 0; c < NCLASS; ++c)
        #pragma unroll
        for (int o = 16; o; o >>= 1) p[c] += __shfl_xor_sync(0xffffffffu, p[c], o);
    if (lane < NCLASS) out[(size_t)n * NCLASS + lane] = p[lane] + b[lane];
}

// ============================================================================
extern "C" void kernel_launch(void* const* d_in, const int* in_sizes, int n_in,
                              void* d_out, int out_size)
{
    const float* feat  = (const float*)d_in[0];
    const float* wih0  = (const float*)d_in[1];
    const float* whh0  = (const float*)d_in[2];
    const float* bih0  = (const float*)d_in[3];
    const float* bhh0  = (const float*)d_in[4];
    const float* wih1  = (const float*)d_in[5];
    const float* whh1  = (const float*)d_in[6];
    const float* bih1  = (const float*)d_in[7];
    const float* bhh1  = (const float*)d_in[8];
    const float* gc1w  = (const float*)d_in[9];
    const float* gc1b  = (const float*)d_in[10];
    const float* gc2w  = (const float*)d_in[11];
    const float* gc2b  = (const float*)d_in[12];
    const float* clfw  = (const float*)d_in[13];
    const float* clfb  = (const float*)d_in[14];
    float* out = (float*)d_out;

    float *pX, *pAdj, *pMu, *pSd, *pD, *pZ, *pY1, *pY2;
    cudaGetSymbolAddress((void**)&pX,  g_X);
    cudaGetSymbolAddress((void**)&pAdj, g_adj);
    cudaGetSymbolAddress((void**)&pMu, g_mu);
    cudaGetSymbolAddress((void**)&pSd, g_sd);
    cudaGetSymbolAddress((void**)&pD,  g_d);
    cudaGetSymbolAddress((void**)&pZ,  g_Z);
    cudaGetSymbolAddress((void**)&pY1, g_Y1);
    cudaGetSymbolAddress((void**)&pY2, g_Y2);

    cudaFuncSetAttribute(lstm_kernel, cudaFuncAttributeMaxDynamicSharedMemorySize,
                         LSTM_SMEM_BYTES);

    // 1) fused 2-layer LSTM -> X (N, T)
    lstm_kernel<<<N_SEQ / SPB, LSTM_THREADS, LSTM_SMEM_BYTES>>>(
        feat, wih0, whh0, bih0, bhh0, wih1, whh1, bih1, bhh1, pX);

    // 2) per-row mean/std
    rowstats_kernel<<<N_SEQ, 128>>>(pX, pMu, pSd);

    // 3) adjacency = corr(X) + I  (Gram matrix with fused epilogue)
    gemm_kernel<128, 128, 8, 8, 8, 1, 0><<<dim3(N_SEQ / 128, N_SEQ / 128), 256>>>(
        pX, pX, pAdj, N_SEQ, N_SEQ, T_LEN, nullptr, nullptr, pMu, pSd);

    // 4) d = rowsum(adj)^-1/2 (0 if rowsum <= 0)
    rowsumd_kernel<<<N_SEQ, 256>>>(pAdj, pD);

    // 5) Z = d ⊙ (X @ gc1_w)
    gemm_kernel<128, 64, 8, 8, 4, 0, 1><<<dim3(HID / 64, N_SEQ / 128), 256>>>(
        pX, gc1w, pZ, N_SEQ, HID, T_LEN, pD, nullptr, nullptr, nullptr);

    // 6) Y1 = relu(d ⊙ (adj @ Z) + gc1_b)
    gemm_kernel<128, 64, 8, 8, 4, 0, 2><<<dim3(HID / 64, N_SEQ / 128), 256>>>(
        pAdj, pZ, pY1, N_SEQ, HID, N_SEQ, pD, gc1b, nullptr, nullptr);

    // 7) Z = d ⊙ (Y1 @ gc2_w)
    gemm_kernel<128, 64, 8, 8, 4, 0, 1><<<dim3(HID / 64, N_SEQ / 128), 256>>>(
        pY1, gc2w, pZ, N_SEQ, HID, HID, pD, nullptr, nullptr, nullptr);

    // 8) Y2 = relu(d ⊙ (adj @ Z) + gc2_b)
    gemm_kernel<128, 64, 8, 8, 4, 0, 2><<<dim3(HID / 64, N_SEQ / 128), 256>>>(
        pAdj, pZ, pY2, N_SEQ, HID, N_SEQ, pD, gc2b, nullptr, nullptr);

    // 9) out = Y2 @ clf_w + clf_b
    clf_kernel<<<N_SEQ / 8, 256>>>(pY2, clfw, clfb, out);
}

// round 7
// speedup vs baseline: 2.2704x; 2.2673x over previous
#include <cuda_runtime.h>
#include <math.h>

#define N_SEQ  4096
#define F_INN  16
#define T_LEN  512
#define HU     64
#define G4     256   // 4*H
#define HID    256
#define NCLASS 10

// ---------------- scratch (no allocation allowed) ----------------
__device__ float g_X[N_SEQ * T_LEN];                  // (N, T) first hidden channel of layer-1
__device__ float g_adj[(size_t)N_SEQ * N_SEQ];        // unnormalized adjacency (corr + I)
__device__ float g_mu[N_SEQ];
__device__ float g_sd[N_SEQ];
__device__ float g_d[N_SEQ];                          // D^-1/2 diag
__device__ float g_Z[N_SEQ * HID];
__device__ float g_Y1[N_SEQ * HID];
__device__ float g_Y2[N_SEQ * HID];

// ---------------- fast math helpers ----------------
__device__ __forceinline__ float ex2a(float x) { float r; asm("ex2.approx.f32 %0,%1;" : "=f"(r) : "f"(x)); return r; }
__device__ __forceinline__ float rcpa(float x) { float r; asm("rcp.approx.f32 %0,%1;" : "=f"(r) : "f"(x)); return r; }
__device__ __forceinline__ float sigf (float x) { return rcpa(1.0f + ex2a(-1.4426950408889634f * x)); }
__device__ __forceinline__ float tanhq(float x) { return 2.0f * rcpa(1.0f + ex2a(-2.8853900817779268f * x)) - 1.0f; }
__device__ __forceinline__ unsigned tf32r(float x) { unsigned u; asm("cvt.rna.tf32.f32 %0,%1;" : "=r"(u) : "f"(x)); return u; }
__device__ __forceinline__ float tf32f(float x) { return __uint_as_float(tf32r(x)); }

__device__ __forceinline__ void mma8(float* c, const uint4& a, unsigned b0, unsigned b1) {
    asm volatile(
        "mma.sync.aligned.m16n8k8.row.col.f32.tf32.tf32.f32 "
        "{%0,%1,%2,%3},{%4,%5,%6,%7},{%8,%9},{%0,%1,%2,%3};"
        : "+f"(c[0]), "+f"(c[1]), "+f"(c[2]), "+f"(c[3])
        : "r"(a.x), "r"(a.y), "r"(a.z), "r"(a.w), "r"(b0), "r"(b1));
}

// ============================================================================
// tf32 tensor-core fused 2-layer LSTM.
// 128 blocks x 128 threads (4 warps). Block owns 32 sequences, all 512 steps.
// Gates G(32x256) = A @ Wcat^T via mma.m16n8k8.tf32, fp32 accumulate.
// A buffer (smem, A-fragment order): 18 k-tiles of 8 cols x 2 rowgroups:
//   tiles 0-1 = x_t (16), tiles 2-9 = h0 (64), tiles 10-17 = h1 (64).
// Weights in B-fragment order, float4 packs 2 k-tiles (b0e,b1e,b0o,b1o).
// Gate col = 4*u + g (torch gate g = col&3; unit u = col>>2).
// Warp w owns gate cols [64w, 64w+64) = units [16w, 16w+16).
// Cell state in fp32 registers (16 cells per thread per layer).
// ============================================================================
#define MB 32
#define LTHREADS 128
#define SWFX 0                     // 32nt * 32 * 4          = 4096 floats
#define SWF0 4096                  // 32nt * 4kp * 32 * 4    = 16384
#define SWF1 20480                 // 32nt * 8kp * 32 * 4    = 32768
#define SA   53248                 // 2rg * 18tile * 32 * 4  = 4608
#define LSMEM_FLOATS 57856
#define LSMEM_BYTES (LSMEM_FLOATS * 4)

__global__ void __launch_bounds__(LTHREADS, 1)
lstm_mma_kernel(const float* __restrict__ feat,
                const float* __restrict__ wih0, const float* __restrict__ whh0,
                const float* __restrict__ bih0, const float* __restrict__ bhh0,
                const float* __restrict__ wih1, const float* __restrict__ whh1,
                const float* __restrict__ bih1, const float* __restrict__ bhh1,
                float* __restrict__ Xout)
{
    extern __shared__ float sm[];
    float* sWfx = sm + SWFX;
    float* sWf0 = sm + SWF0;
    float* sWf1 = sm + SWF1;
    float* sA   = sm + SA;

    const int tid  = threadIdx.x;
    const int lane = tid & 31;
    const int w    = tid >> 5;
    const int t4   = lane & 3;       // threadID in group
    const int gq   = lane >> 2;      // groupID
    const int nbase = blockIdx.x * MB;

    // ---- stage weights into B-fragment order (tf32-rounded) ----
    // slot s: 0=b0(k-tile even) 1=b1(even) 2=b0(odd) 3=b1(odd)
    for (int i = tid; i < 32 * 32 * 4; i += LTHREADS) {          // Wfx (1 kpair)
        int s = i & 3, ln = (i >> 2) & 31, nt = i >> 7;
        int tt = ln & 3, gg = ln >> 2;
        int krow = (s >> 1) * 8 + tt + (s & 1) * 4;              // 0..15
        int c = nt * 8 + gg, u = c >> 2, g = c & 3;
        sWfx[i] = tf32f(wih0[(g * 64 + u) * F_INN + krow]);
    }
    for (int i = tid; i < 32 * 4 * 32 * 4; i += LTHREADS) {      // Wf0 (4 kpairs)
        int s = i & 3, ln = (i >> 2) & 31, kp = (i >> 7) & 3, nt = i >> 9;
        int tt = ln & 3, gg = ln >> 2;
        int krow = (2 * kp + (s >> 1)) * 8 + tt + (s & 1) * 4;   // 0..63
        int c = nt * 8 + gg, u = c >> 2, g = c & 3;
        sWf0[i] = tf32f(whh0[(g * 64 + u) * HU + krow]);
    }
    for (int i = tid; i < 32 * 8 * 32 * 4; i += LTHREADS) {      // Wf1 (8 kpairs)
        int s = i & 3, ln = (i >> 2) & 31, kp = (i >> 7) & 7, nt = i >> 10;
        int tt = ln & 3, gg = ln >> 2;
        int r = (2 * kp + (s >> 1)) * 8 + tt + (s & 1) * 4;      // 0..127
        int c = nt * 8 + gg, u = c >> 2, g = c & 3;
        float v = (r < 64) ? wih1[(g * 64 + u) * HU + r]
                           : whh1[(g * 64 + u) * HU + (r - 64)];
        sWf1[i] = tf32f(v);
    }
    for (int i = tid; i < 2 * 18 * 32 * 4; i += LTHREADS) sA[i] = 0.0f;

    // ---- biases into registers (fp32, seed the accumulators) ----
    float br0[16], br1[16];
    #pragma unroll
    for (int j = 0; j < 8; ++j)
        #pragma unroll
        for (int p = 0; p < 2; ++p) {
            int col = 64 * w + 8 * j + 2 * t4 + p;
            int u = col >> 2, g = col & 3, jj = g * 64 + u;
            br0[j * 2 + p] = bih0[jj] + bhh0[jj];
            br1[j * 2 + p] = bih1[jj] + bhh1[jj];
        }

    // ---- x prefetch: thread owns (seq row xs, features xf..xf+3) ----
    const int xs = tid >> 2;            // seq row 0..31
    const int xf = (tid & 3) * 4;       // feature base 0,4,8,12
    const float* fp = feat + (size_t)(nbase + xs) * (F_INN * T_LEN);
    float xr[4];
    #pragma unroll
    for (int q = 0; q < 4; ++q) xr[q] = fp[(xf + q) * T_LEN + 0];

    __syncthreads();

    float cst0[16], cst1[16];
    #pragma unroll
    for (int i = 0; i < 16; ++i) { cst0[i] = 0.0f; cst1[i] = 0.0f; }

    float C[2][8][4];

#define LDA(rg, tile) (*(const uint4*)&sA[(((rg) * 18 + (tile)) * 32 + lane) * 4])

#define MMA_KPAIR(tb, BPTR, bidx)                                          \
    {                                                                      \
        uint4 ae0 = LDA(0, tb), ao0 = LDA(0, (tb) + 1);                    \
        uint4 ae1 = LDA(1, tb), ao1 = LDA(1, (tb) + 1);                    \
        _Pragma("unroll")                                                  \
        for (int j = 0; j < 8; ++j) {                                      \
            uint4 b = *(const uint4*)&(BPTR)[(bidx)];                      \
            mma8(C[0][j], ae0, b.x, b.y);                                  \
            mma8(C[1][j], ae1, b.x, b.y);                                  \
            mma8(C[0][j], ao0, b.z, b.w);                                  \
            mma8(C[1][j], ao1, b.z, b.w);                                  \
        }                                                                  \
    }

    // C-fragment cell (rg,j): rows rg*16+gq (c0,c1) / rg*16+gq+8 (c2,c3),
    // cols 64w+8j+2t4 / +1. Pair (t4 xor 1) swap gives each thread the full
    // i,f,g,o of ONE (row, unit): even lane -> row gq, odd -> row gq+8;
    // unit uloc = 2j + (t4>>1) within warp.
#define ACT(cst, base, DO_OUT)                                             \
    {                                                                      \
        _Pragma("unroll")                                                  \
        for (int rg = 0; rg < 2; ++rg) {                                   \
            _Pragma("unroll")                                              \
            for (int j = 0; j < 8; ++j) {                                  \
                float x0 = C[rg][j][0], x1 = C[rg][j][1];                  \
                float x2 = C[rg][j][2], x3 = C[rg][j][3];                  \
                float y0 = __shfl_xor_sync(0xffffffffu, x0, 1);            \
                float y1 = __shfl_xor_sync(0xffffffffu, x1, 1);            \
                float y2 = __shfl_xor_sync(0xffffffffu, x2, 1);            \
                float y3 = __shfl_xor_sync(0xffffffffu, x3, 1);            \
                int oddl = t4 & 1;                                         \
                float gi = oddl ? y2 : x0;                                 \
                float gf = oddl ? y3 : x1;                                 \
                float gg = oddl ? x2 : y0;                                 \
                float go = oddl ? x3 : y1;                                 \
                float cc = sigf(gf) * (cst)[rg * 8 + j]                    \
                         + sigf(gi) * tanhq(gg);                           \
                (cst)[rg * 8 + j] = cc;                                    \
                float h = sigf(go) * tanhq(cc);                            \
                int uloc = 2 * j + (t4 >> 1);                              \
                int tile = (base) + 2 * w + (uloc >> 3);                   \
                int ct = uloc & 7, tA = ct & 3, sb = (ct >> 2) * 2;        \
                int sidx = ((rg * 18 + tile) * 32 + gq * 4 + tA) * 4       \
                           + sb + oddl;                                    \
                sA[sidx] = __uint_as_float(tf32r(h));                      \
                if (DO_OUT && w == 0 && uloc == 0) {                       \
                    int row = rg * 16 + gq + (oddl ? 8 : 0);               \
                    Xout[(size_t)(nbase + row) * T_LEN + t] = h;           \
                }                                                          \
            }                                                              \
        }                                                                  \
    }

    for (int t = 0; t < T_LEN; ++t) {
        // ---- store x_t into A-fragment buffer (tiles 0-1) ----
        #pragma unroll
        for (int q = 0; q < 4; ++q) {
            int f = xf + q, tile = f >> 3, ct = f & 7;
            int tA = ct & 3, sb = (ct >> 2) * 2;
            int grow = xs & 15, rg = xs >> 4;
            int sidx = ((rg * 18 + tile) * 32 + (grow & 7) * 4 + tA) * 4
                       + sb + (grow >= 8 ? 1 : 0);
            sA[sidx] = __uint_as_float(tf32r(xr[q]));
        }
        __syncthreads();                                   // BAR A

        // ---- layer 0: G = [x | h0] @ W0cat^T ----
        #pragma unroll
        for (int j = 0; j < 8; ++j) {
            C[0][j][0] = br0[2 * j]; C[0][j][1] = br0[2 * j + 1];
            C[0][j][2] = br0[2 * j]; C[0][j][3] = br0[2 * j + 1];
            C[1][j][0] = br0[2 * j]; C[1][j][1] = br0[2 * j + 1];
            C[1][j][2] = br0[2 * j]; C[1][j][3] = br0[2 * j + 1];
        }
        MMA_KPAIR(0, sWfx, ((w * 8 + j) * 32 + lane) * 4)
        #pragma unroll
        for (int kp = 0; kp < 4; ++kp)
            MMA_KPAIR(2 + 2 * kp, sWf0, (((w * 8 + j) * 4 + kp) * 32 + lane) * 4)
        __syncthreads();                                   // BAR B

        ACT(cst0, 2, 0)                                    // h0 -> tiles 2..9
        if (t + 1 < T_LEN) {
            #pragma unroll
            for (int q = 0; q < 4; ++q) xr[q] = fp[(xf + q) * T_LEN + (t + 1)];
        }
        __syncthreads();                                   // BAR C

        // ---- layer 1: G = [h0 | h1] @ W1cat^T ----
        #pragma unroll
        for (int j = 0; j < 8; ++j) {
            C[0][j][0] = br1[2 * j]; C[0][j][1] = br1[2 * j + 1];
            C[0][j][2] = br1[2 * j]; C[0][j][3] = br1[2 * j + 1];
            C[1][j][0] = br1[2 * j]; C[1][j][1] = br1[2 * j + 1];
            C[1][j][2] = br1[2 * j]; C[1][j][3] = br1[2 * j + 1];
        }
        #pragma unroll
        for (int kp = 0; kp < 8; ++kp)
            MMA_KPAIR(2 + 2 * kp, sWf1, (((w * 8 + j) * 8 + kp) * 32 + lane) * 4)
        __syncthreads();                                   // BAR D

        ACT(cst1, 10, 1)                                   // h1 -> tiles 10..17 + X out
    }
#undef LDA
#undef MMA_KPAIR
#undef ACT
}

// ============================================================================
// Row stats: mu, std per row of X (N, T)
// ============================================================================
__global__ void rowstats_kernel(const float* __restrict__ X,
                                float* __restrict__ mu, float* __restrict__ sd)
{
    __shared__ float s1[4], s2[4];
    int n = blockIdx.x;
    float a = 0.f, b = 0.f;
    for (int i = threadIdx.x; i < T_LEN; i += 128) {
        float v = X[(size_t)n * T_LEN + i];
        a += v; b += v * v;
    }
    #pragma unroll
    for (int o = 16; o; o >>= 1) {
        a += __shfl_xor_sync(0xffffffffu, a, o);
        b += __shfl_xor_sync(0xffffffffu, b, o);
    }
    int w = threadIdx.x >> 5;
    if ((threadIdx.x & 31) == 0) { s1[w] = a; s2[w] = b; }
    __syncthreads();
    if (threadIdx.x == 0) {
        a = s1[0] + s1[1] + s1[2] + s1[3];
        b = s2[0] + s2[1] + s2[2] + s2[3];
        float m = a * (1.0f / T_LEN);
        float var = b * (1.0f / T_LEN) - m * m;
        if (var < 0.f) var = 0.f;
        mu[n] = m;
        sd[n] = sqrtf(var);
    }
}

// ============================================================================
// Generic register-tiled fp32 GEMM. C = A(MxK) @ B(KxN)  (TB=1: B = Bphys^T,
// Bphys is NxK row-major). Epilogues:
//   EPI 0: adjacency from Gram matrix (needs mu, sd)
//   EPI 1: scale rows by dd[row]
//   EPI 2: relu(dd[row]*v + bias[col])
// ============================================================================
template<int BM, int BN, int BK, int TM, int TN, int TB, int EPI>
__global__ void gemm_kernel(const float* __restrict__ A, const float* __restrict__ B,
                            float* __restrict__ C, int M, int N, int K,
                            const float* __restrict__ dd, const float* __restrict__ bias,
                            const float* __restrict__ mu, const float* __restrict__ sd)
{
    constexpr int TX = BN / TN;
    constexpr int TY = BM / TM;
    constexpr int THREADS = TX * TY;
    __shared__ float As[BK][BM + 4];
    __shared__ float Bs[BK][BN + 4];

    const int t  = threadIdx.x;
    const int bm = blockIdx.y * BM;
    const int bn = blockIdx.x * BN;
    const int tx = t % TX;
    const int ty = t / TX;

    float acc[TM][TN];
    #pragma unroll
    for (int i = 0; i < TM; ++i)
        #pragma unroll
        for (int j = 0; j < TN; ++j) acc[i][j] = 0.f;

    for (int k0 = 0; k0 < K; k0 += BK) {
        constexpr int A4 = BM * BK / 4;
        #pragma unroll
        for (int i = t; i < A4; i += THREADS) {
            int row = i / (BK / 4), kc = (i % (BK / 4)) * 4;
            float4 v = *(const float4*)&A[(size_t)(bm + row) * K + k0 + kc];
            As[kc + 0][row] = v.x; As[kc + 1][row] = v.y;
            As[kc + 2][row] = v.z; As[kc + 3][row] = v.w;
        }
        if (TB == 0) {
            constexpr int B4 = BK * BN / 4;
            #pragma unroll
            for (int i = t; i < B4; i += THREADS) {
                int row = i / (BN / 4), nc = (i % (BN / 4)) * 4;
                float4 v = *(const float4*)&B[(size_t)(k0 + row) * N + bn + nc];
                Bs[row][nc + 0] = v.x; Bs[row][nc + 1] = v.y;
                Bs[row][nc + 2] = v.z; Bs[row][nc + 3] = v.w;
            }
        } else {
            constexpr int B4 = BN * BK / 4;
            #pragma unroll
            for (int i = t; i < B4; i += THREADS) {
                int col = i / (BK / 4), kc = (i % (BK / 4)) * 4;
                float4 v = *(const float4*)&B[(size_t)(bn + col) * K + k0 + kc];
                Bs[kc + 0][col] = v.x; Bs[kc + 1][col] = v.y;
                Bs[kc + 2][col] = v.z; Bs[kc + 3][col] = v.w;
            }
        }
        __syncthreads();
        #pragma unroll
        for (int k = 0; k < BK; ++k) {
            float ra[TM], rb[TN];
            #pragma unroll
            for (int i = 0; i < TM; ++i) ra[i] = As[k][ty * TM + i];
            #pragma unroll
            for (int j = 0; j < TN; ++j) rb[j] = Bs[k][tx * TN + j];
            #pragma unroll
            for (int i = 0; i < TM; ++i)
                #pragma unroll
                for (int j = 0; j < TN; ++j) acc[i][j] += ra[i] * rb[j];
        }
        __syncthreads();
    }

    #pragma unroll
    for (int i = 0; i < TM; ++i) {
        int row = bm + ty * TM + i;
        #pragma unroll
        for (int j = 0; j < TN; ++j) {
            int col = bn + tx * TN + j;
            float v = acc[i][j];
            if (EPI == 0) {
                float cov = v * (1.0f / T_LEN) - mu[row] * mu[col];
                float den = sd[row] * sd[col];
                v = (den == 0.0f) ? 0.0f : cov / den;
                if (row == col) v += 1.0f;
            } else if (EPI == 1) {
                v *= dd[row];
            } else if (EPI == 2) {
                v = dd[row] * v + bias[col];
                v = fmaxf(v, 0.0f);
            }
            C[(size_t)row * N + col] = v;
        }
    }
}

// ============================================================================
// Row-sum of adjacency -> d = rs>0 ? rs^-1/2 : 0
// ============================================================================
__global__ void rowsumd_kernel(const float* __restrict__ adj, float* __restrict__ d)
{
    __shared__ float sr[8];
    int n = blockIdx.x;
    float a = 0.f;
    for (int j = threadIdx.x; j < N_SEQ; j += 256) a += adj[(size_t)n * N_SEQ + j];
    #pragma unroll
    for (int o = 16; o; o >>= 1) a += __shfl_xor_sync(0xffffffffu, a, o);
    int w = threadIdx.x >> 5;
    if ((threadIdx.x & 31) == 0) sr[w] = a;
    __syncthreads();
    if (threadIdx.x == 0) {
        a = 0.f;
        #pragma unroll
        for (int i = 0; i < 8; ++i) a += sr[i];
        d[n] = (a > 0.0f) ? (1.0f / sqrtf(a)) : 0.0f;
    }
}

// ============================================================================
// Classifier: out = Y2 @ clf_w + clf_b ; one warp per row
// ============================================================================
__global__ void clf_kernel(const float* __restrict__ Y, const float* __restrict__ W,
                           const float* __restrict__ b, float* __restrict__ out)
{
    int warp = threadIdx.x >> 5, lane = threadIdx.x & 31;
    int n = blockIdx.x * 8 + warp;
    float p[NCLASS];
    #pragma unroll
    for (int c = 0; c < NCLASS; ++c) p[c] = 0.f;
    for (int k = lane; k < HID; k += 32) {
        float x = Y[(size_t)n * HID + k];
        #pragma unroll
        for (int c = 0; c < NCLASS; ++c) p[c] += x * W[k * NCLASS + c];
    }
    #pragma unroll
    for (int c = 0; c < NCLASS; ++c)
        #pragma unroll
        for (int o = 16; o; o >>= 1) p[c] += __shfl_xor_sync(0xffffffffu, p[c], o);
    if (lane < NCLASS) out[(size_t)n * NCLASS + lane] = p[lane] + b[lane];
}

// ============================================================================
extern "C" void kernel_launch(void* const* d_in, const int* in_sizes, int n_in,
                              void* d_out, int out_size)
{
    const float* feat  = (const float*)d_in[0];
    const float* wih0  = (const float*)d_in[1];
    const float* whh0  = (const float*)d_in[2];
    const float* bih0  = (const float*)d_in[3];
    const float* bhh0  = (const float*)d_in[4];
    const float* wih1  = (const float*)d_in[5];
    const float* whh1  = (const float*)d_in[6];
    const float* bih1  = (const float*)d_in[7];
    const float* bhh1  = (const float*)d_in[8];
    const float* gc1w  = (const float*)d_in[9];
    const float* gc1b  = (const float*)d_in[10];
    const float* gc2w  = (const float*)d_in[11];
    const float* gc2b  = (const float*)d_in[12];
    const float* clfw  = (const float*)d_in[13];
    const float* clfb  = (const float*)d_in[14];
    float* out = (float*)d_out;

    float *pX, *pAdj, *pMu, *pSd, *pD, *pZ, *pY1, *pY2;
    cudaGetSymbolAddress((void**)&pX,  g_X);
    cudaGetSymbolAddress((void**)&pAdj, g_adj);
    cudaGetSymbolAddress((void**)&pMu, g_mu);
    cudaGetSymbolAddress((void**)&pSd, g_sd);
    cudaGetSymbolAddress((void**)&pD,  g_d);
    cudaGetSymbolAddress((void**)&pZ,  g_Z);
    cudaGetSymbolAddress((void**)&pY1, g_Y1);
    cudaGetSymbolAddress((void**)&pY2, g_Y2);

    cudaFuncSetAttribute(lstm_mma_kernel, cudaFuncAttributeMaxDynamicSharedMemorySize,
                         LSMEM_BYTES);

    // 1) fused 2-layer tf32 tensor-core LSTM -> X (N, T)
    lstm_mma_kernel<<<N_SEQ / MB, LTHREADS, LSMEM_BYTES>>>(
        feat, wih0, whh0, bih0, bhh0, wih1, whh1, bih1, bhh1, pX);

    // 2) per-row mean/std
    rowstats_kernel<<<N_SEQ, 128>>>(pX, pMu, pSd);

    // 3) adjacency = corr(X) + I  (Gram matrix with fused epilogue)
    gemm_kernel<128, 128, 8, 8, 8, 1, 0><<<dim3(N_SEQ / 128, N_SEQ / 128), 256>>>(
        pX, pX, pAdj, N_SEQ, N_SEQ, T_LEN, nullptr, nullptr, pMu, pSd);

    // 4) d = rowsum(adj)^-1/2 (0 if rowsum <= 0)
    rowsumd_kernel<<<N_SEQ, 256>>>(pAdj, pD);

    // 5) Z = d ⊙ (X @ gc1_w)
    gemm_kernel<128, 64, 8, 8, 4, 0, 1><<<dim3(HID / 64, N_SEQ / 128), 256>>>(
        pX, gc1w, pZ, N_SEQ, HID, T_LEN, pD, nullptr, nullptr, nullptr);

    // 6) Y1 = relu(d ⊙ (adj @ Z) + gc1_b)
    gemm_kernel<128, 64, 8, 8, 4, 0, 2><<<dim3(HID / 64, N_SEQ / 128), 256>>>(
        pAdj, pZ, pY1, N_SEQ, HID, N_SEQ, pD, gc1b, nullptr, nullptr);

    // 7) Z = d ⊙ (Y1 @ gc2_w)
    gemm_kernel<128, 64, 8, 8, 4, 0, 1><<<dim3(HID / 64, N_SEQ / 128), 256>>>(
        pY1, gc2w, pZ, N_SEQ, HID, HID, pD, nullptr, nullptr, nullptr);

    // 8) Y2 = relu(d ⊙ (adj @ Z) + gc2_b)
    gemm_kernel<128, 64, 8, 8, 4, 0, 2><<<dim3(HID / 64, N_SEQ / 128), 256>>>(
        pAdj, pZ, pY2, N_SEQ, HID, N_SEQ, pD, gc2b, nullptr, nullptr);

    // 9) out = Y2 @ clf_w + clf_b
    clf_kernel<<<N_SEQ / 8, 256>>>(pY2, clfw, clfb, out);
}